// round 12
// baseline (speedup 1.0000x reference)
#include <cuda_runtime.h>

#define HH    512
#define WW    512
#define HW    (HH * WW)
#define NKW   32
#define NK    1024
#define BATCH 64
#define RP    36          // padded lane-row (floats): bank-spread rows

// Init: out[b,n] = bias[n], vectorized. Full overwrite -> replay idempotent.
__global__ __launch_bounds__(256) void bslc_init(
    const float4* __restrict__ bias4, float4* __restrict__ out4)
{
    const int idx = blockIdx.x * 256 + threadIdx.x;   // 16384 float4 slots
    out4[idx] = bias4[idx & 255];
}

// Aligned-scatter kernel. Block = one 32px x 16row ALIGNED region of the
// ACTUAL image (padding pixels are zero -> never touched). Region (g,k):
// rows [16g,16g+16), cols [32k,32k+32). Every x warp-load is 4 full
// 128B lines (4 wavefronts, vs ~12 for cell-aligned tiles).
//
// Pixel (y,x) -> padded (y+8,x+8): windows rows {cy-1,cy}, cols {cx-1,cx}
// with cy=(y+8)>>4, cx=(x+8)>>4; kernel offs dy=y+8-16*wr, dx=x+8-16*wc.
// Warp = (quarter qr = 4-row band, bslot = batch half). Lane owns one
// float4: f=lane&7 (col quad), r=lane>>3 (row in band). cy is uniform per
// warp; cx = 2k + cxo, cxo=(f+2)>>2 in {0,1,2}. Lane holds 4 weight float4
// (2 wrows x 2 wcols, zero if window invalid).
//
// Per 4-batch pass: 4 aligned LDG.128, 16 FMA/batch, 4 STS to lane-permuted
// slots (slot=4f+r -> cxo groups are CONTIGUOUS slot ranges, conflict-free).
// Subtask stage: 256 threads sum contiguous slot ranges per window-col;
// final stage: 96 threads combine quarters and atomicAdd (12 windows x 64
// batches per block into bias-initialized out).
__global__ __launch_bounds__(256, 4) void bslc_main(
    const float* __restrict__ x,       // (64,1,512,512)
    const float* __restrict__ weight,  // (NK,1024)
    float* __restrict__ out)           // (64,NK) = bias-initialized
{
    // [bslot][bp][wr'][wc'][qr][slot+pad] : qr stride 36 -> bank-spread
    __shared__ __align__(16) float sred[2][4][2][2][4][RP];   // 18.4KB
    __shared__ float stage[2][4][3][4][4];                    // 1.5KB

    const int g = blockIdx.x >> 4;     // row-group 0..31
    const int k = blockIdx.x & 15;     // col-span  0..15
    const int tid  = threadIdx.x;
    const int lane = tid & 31;
    const int warp = tid >> 5;
    const int qr    = warp >> 1;       // 4-row band 0..3
    const int bslot = warp & 1;        // batch half

    const int f = lane & 7;            // float4 index in 32px row
    const int r = lane >> 3;           // row within band
    const int slot = f * 4 + r;        // lane-permutation for smem scatter

    const int cxo = (f + 2) >> 2;      // 0,1,2 : cx = 2k + cxo
    const int y    = 16 * g + 4 * qr + r;
    const int xcol = 32 * k + 4 * f;
    const int cy   = g + (qr >> 1);

    // Lane's 4 weight float4s (wr' x wc'), zero for invalid windows
    float4 w[2][2];
#pragma unroll
    for (int wr = 0; wr < 2; wr++)
#pragma unroll
        for (int wc = 0; wc < 2; wc++) {
            const int wrow = cy - 1 + wr;
            const int wcol = 2 * k - 1 + cxo + wc;
            float4 ww = make_float4(0.f, 0.f, 0.f, 0.f);
            if (wrow >= 0 && wrow < 32 && wcol >= 0 && wcol < 32) {
                const int dy = y    + 8 - 16 * wrow;
                const int dx = xcol + 8 - 16 * wcol;
                ww = *reinterpret_cast<const float4*>(
                        weight + (wrow * NKW + wcol) * 1024 + dy * 32 + dx);
            }
            w[wr][wc] = ww;
        }

    const float* __restrict__ xb =
        x + (size_t)(bslot * 32) * HW + y * WW + xcol;

    for (int pass = 0; pass < 8; pass++) {
        // 4 aligned LDG.128 (each = 4 full lines, 4 wavefronts)
        float4 xv[4];
#pragma unroll
        for (int bp = 0; bp < 4; bp++)
            xv[bp] = *reinterpret_cast<const float4*>(
                         xb + (size_t)(pass * 4 + bp) * HW);

#pragma unroll
        for (int bp = 0; bp < 4; bp++)
#pragma unroll
            for (int wr = 0; wr < 2; wr++)
#pragma unroll
                for (int wc = 0; wc < 2; wc++) {
                    const float4 ww = w[wr][wc];
                    const float s =
                        fmaf(xv[bp].x, ww.x,
                        fmaf(xv[bp].y, ww.y,
                        fmaf(xv[bp].z, ww.z, xv[bp].w * ww.w)));
                    sred[bslot][bp][wr][wc][qr][slot] = s;  // conflict-free
                }
        __syncthreads();

        // Subtask: 256 threads = (bslot,bp) x (qr2, wr2, wci).
        // Window col 2k-1+wci gets (wc'=0, cxo=wci) + (wc'=1, cxo=wci-1);
        // cxo groups are contiguous slot ranges (f-major slots):
        //   cxo=0 -> f4 [0,2), cxo=1 -> [2,6), cxo=2 -> [6,8)
        {
            const int sb  = tid >> 5;          // bslot*4 + bp
            const int bs2 = sb >> 2, bp2 = sb & 3;
            const int st  = tid & 31;
            const int q2  = st >> 3;
            const int w2  = (st >> 2) & 1;
            const int wci = st & 3;

            const int l0 = (wci == 0) ? 0 : (wci == 1) ? 2 : (wci == 2) ? 6 : 8;
            const int h0 = (wci == 0) ? 2 : (wci == 1) ? 6 : (wci == 2) ? 8 : 8;
            const int l1 = (wci == 0) ? 8 : (wci == 1) ? 0 : (wci == 2) ? 2 : 6;
            const int h1 = (wci == 0) ? 8 : (wci == 1) ? 2 : (wci == 2) ? 6 : 8;

            const float4* r0 = reinterpret_cast<const float4*>(
                                   &sred[bs2][bp2][w2][0][q2][0]);
            const float4* r1 = reinterpret_cast<const float4*>(
                                   &sred[bs2][bp2][w2][1][q2][0]);
            float s = 0.f;
#pragma unroll 1
            for (int i = l0; i < h0; i++) {
                const float4 v = r0[i]; s += (v.x + v.y) + (v.z + v.w);
            }
#pragma unroll 1
            for (int i = l1; i < h1; i++) {
                const float4 v = r1[i]; s += (v.x + v.y) + (v.z + v.w);
            }
            const int j = (q2 < 2) ? w2 : w2 + 1;   // window-row index g-1+j
            stage[bs2][bp2][j][wci][q2] = s;
        }
        __syncthreads();

        // Final: 96 threads -> (bslot,bp) x (j in 0..2) x (wci in 0..3)
        if (tid < 96) {
            const int wci  = tid & 3;
            const int rest = tid >> 2;         // 0..23
            const int j    = rest % 3;
            const int sb   = rest / 3;         // 0..7
            const int bs2  = sb >> 2, bp2 = sb & 3;
            float s;
            if (j == 0)
                s = stage[bs2][bp2][0][wci][0] + stage[bs2][bp2][0][wci][1];
            else if (j == 2)
                s = stage[bs2][bp2][2][wci][2] + stage[bs2][bp2][2][wci][3];
            else
                s = (stage[bs2][bp2][1][wci][0] + stage[bs2][bp2][1][wci][1])
                  + (stage[bs2][bp2][1][wci][2] + stage[bs2][bp2][1][wci][3]);

            const int wrow = g - 1 + j;
            const int wcol = 2 * k - 1 + wci;
            if (wrow >= 0 && wrow < 32 && wcol >= 0 && wcol < 32) {
                const int b = bs2 * 32 + pass * 4 + bp2;
                atomicAdd(out + (size_t)b * NK + wrow * NKW + wcol, s);
            }
        }
        // Next pass: STS->sred safe (subtask reads done before sync #2);
        // stage rewrite happens after next sync #1 -> final reads are safe.
        __syncthreads();
    }
}

extern "C" void kernel_launch(void* const* d_in, const int* in_sizes, int n_in,
                              void* d_out, int out_size)
{
    const float* x      = (const float*)d_in[0];   // (64,1,512,512) fp32
    const float* weight = (const float*)d_in[1];   // (1024,1024)    fp32
    const float* bias   = (const float*)d_in[2];   // (1024,)        fp32
    float*       out    = (float*)d_out;           // (64,32,32)     fp32

    bslc_init<<<(BATCH * NK) / (256 * 4), 256>>>(
        (const float4*)bias, (float4*)out);

    bslc_main<<<32 * 16, 256>>>(x, weight, out);   // 512 aligned regions
}